// round 8
// baseline (speedup 1.0000x reference)
#include <cuda_runtime.h>
#include <cuda_bf16.h>
#include <math.h>
#include <stdint.h>

#define NB 256
#define NS 64
#define NT 20
#define NE 100
#define NEP 128
#define NH 1024
#define NV 32000
#define N3H (3 * NH)
#define TD (NT - 1)
#define BH (NB * NH)
#define NROWS (NB * TD)       // 4864 decoder rows
#define NTILL (NV / 256)      // 125 col tiles of logits (256-wide)

typedef __nv_bfloat16 bf16;

// ------------------------- scratch (device globals) -------------------------
__device__ float g_gi_enc[(size_t)NB * NS * N3H];   // 201 MB
__device__ float g_gh[NB * N3H];
__device__ float g_hf[BH];          // permuted fp32 encoder h (in-place)
__device__ float g_hd[BH];
__device__ float g_ctx[BH];
__device__ float g_ctxgi[NB * N3H];
__device__ float g_gidec[(size_t)NROWS * N3H];      // 60 MB
__device__ float2 g_cepart[(size_t)NROWS * NTILL];  // 4.9 MB
__device__ float g_tgt[NROWS];
__device__ float g_ce[NROWS];
__device__ float g_mask[NROWS];
__device__ int g_perm[NB];
__device__ int g_cnt[NS];

__device__ bf16 g_embb[(size_t)NB * NS * NEP];
__device__ bf16 g_dembb[(size_t)NROWS * NEP];
__device__ bf16 g_hb0[BH];          // permuted bf16 encoder h (in-place)
__device__ bf16 g_ctxb[BH];
__device__ bf16 g_hall[(size_t)TD * BH];
__device__ bf16 wb_hh_e[(size_t)N3H * NH];
__device__ bf16 wb_hh_d[(size_t)N3H * NH];
__device__ bf16 wb_fc[(size_t)NV * NH];
__device__ bf16 wb_ih_e[(size_t)N3H * NEP];
__device__ bf16 wb_ihd_emb[(size_t)N3H * NEP];
__device__ bf16 wb_ihd_ctx[(size_t)N3H * NH];

// ------------------------- helpers -------------------------------------------
__device__ __forceinline__ void cpasync16(void* smem, const void* gmem)
{
    uint32_t s = (uint32_t)__cvta_generic_to_shared(smem);
    asm volatile("cp.async.cg.shared.global [%0], [%1], 16;\n" ::"r"(s), "l"(gmem));
}

#define LDM4(r0, r1, r2, r3, smaddr)                                            \
    asm volatile("ldmatrix.sync.aligned.m8n8.x4.shared.b16 {%0,%1,%2,%3}, [%4];" \
                 : "=r"(r0), "=r"(r1), "=r"(r2), "=r"(r3) : "r"(smaddr))

#define MMA16816(c, a, b0, b1)                                                   \
    asm volatile("mma.sync.aligned.m16n8k16.row.col.f32.bf16.bf16.f32 "          \
                 "{%0,%1,%2,%3}, {%4,%5,%6,%7}, {%8,%9}, {%0,%1,%2,%3};"         \
                 : "+f"(c[0]), "+f"(c[1]), "+f"(c[2]), "+f"(c[3])                \
                 : "r"(a[0]), "r"(a[1]), "r"(a[2]), "r"(a[3]), "r"(b0), "r"(b1))

__device__ __forceinline__ float sigmoidf_(float x) {
    return 1.0f / (1.0f + __expf(-x));
}

// ------------------------- conversions / gathers ------------------------------
__global__ __launch_bounds__(256) void f2bf(const float* __restrict__ in,
                                            bf16* __restrict__ out, int n)
{
    for (int i = blockIdx.x * blockDim.x + threadIdx.x; i < n;
         i += gridDim.x * blockDim.x)
        out[i] = __float2bfloat16(in[i]);
}

__global__ __launch_bounds__(256) void f2bf_slice(
    const float* __restrict__ in, int ldin, int koff, int kin,
    bf16* __restrict__ out, int kout, int rows)
{
    int n = rows * kout;
    for (int i = blockIdx.x * blockDim.x + threadIdx.x; i < n;
         i += gridDim.x * blockDim.x) {
        int r = i / kout, c = i % kout;
        out[i] = (c < kin) ? __float2bfloat16(in[(size_t)r * ldin + koff + c])
                           : __float2bfloat16(0.0f);
    }
}

__global__ __launch_bounds__(256) void gather_emb_enc_bf(
    const int* __restrict__ tokens, const float* __restrict__ table,
    bf16* __restrict__ out)
{
    int n = NB * NS * NEP;
    for (int i = blockIdx.x * blockDim.x + threadIdx.x; i < n;
         i += gridDim.x * blockDim.x) {
        int c = i % NEP, m = i / NEP;
        float v = 0.0f;
        if (c < NE) v = table[tokens[m] * NE + c];
        out[i] = __float2bfloat16(v);
    }
}

__global__ __launch_bounds__(256) void gather_demb_bf(
    const int* __restrict__ targets, const float* __restrict__ E_dec,
    bf16* __restrict__ out)
{
    int n = NROWS * NEP;
    for (int i = blockIdx.x * blockDim.x + threadIdx.x; i < n;
         i += gridDim.x * blockDim.x) {
        int c = i % NEP, m = i / NEP;
        int t = m % TD, b = m / TD;
        float v = 0.0f;
        if (c < NE) {
            int tok = (t == 0) ? 1 : targets[b * NT + t];
            v = E_dec[tok * NE + c];
        }
        out[i] = __float2bfloat16(v);
    }
}

// ---- batch permutation sorted by length (desc), cnt[t] = #{len >= t+1} ------
__global__ __launch_bounds__(NB) void build_perm(
    const int* __restrict__ lengths, int* __restrict__ perm,
    int* __restrict__ cnt)
{
    __shared__ int slen[NB];
    int tid = threadIdx.x;
    slen[tid] = lengths[tid];
    __syncthreads();
    int L = slen[tid];
    int rank = 0;
    for (int i = 0; i < NB; i++) {
        int Li = slen[i];
        if (Li > L || (Li == L && i < tid)) rank++;
    }
    perm[rank] = tid;
    if (tid < NS) {
        int c = 0;
        for (int i = 0; i < NB; i++) c += (slen[i] >= tid + 1);
        cnt[tid] = c;
    }
}

__global__ __launch_bounds__(256) void permute_h0(
    const float* __restrict__ h0, const int* __restrict__ perm,
    float* __restrict__ hf, bf16* __restrict__ hb)
{
    int idx = blockIdx.x * blockDim.x + threadIdx.x;
    int i = idx >> 10, j = idx & (NH - 1);
    float v = h0[(size_t)perm[i] * NH + j];
    hf[idx] = v;
    hb[idx] = __float2bfloat16(v);
}

// ------------- 64x64x32 GEMM, 4-stage cp.async pipeline (recurrence) ----------
#define TBM 64
#define TBN 64
#define TBK 32

__global__ __launch_bounds__(128) void hgemm(
    int M, int N, int K,
    const bf16* __restrict__ A, int lda,
    const bf16* __restrict__ B, int ldb,
    const float* __restrict__ bias,
    float* __restrict__ C, int ldc,
    const int* __restrict__ cnt, int t)
{
    __shared__ __align__(16) bf16 As[4][TBM][40];
    __shared__ __align__(16) bf16 Bs[4][TBN][40];

    int row0 = blockIdx.y * TBM;
    if (cnt != nullptr && row0 >= cnt[t]) return;   // length-sorted early exit

    int tid = threadIdx.x;
    int warp = tid >> 5, lane = tid & 31;
    int wm = warp >> 1, wn = warp & 1;
    int col0 = blockIdx.x * TBN;

    float acc[2][4][4] = {};
    int KT = K / TBK;

#pragma unroll
    for (int s = 0; s < 3; s++) {
        int kb = s * TBK;
#pragma unroll
        for (int i = 0; i < 2; i++) {
            int v = tid + i * 128;
            int r = v >> 2, c = (v & 3) * 8;
            cpasync16(&As[s][r][c], A + (size_t)(row0 + r) * lda + kb + c);
            cpasync16(&Bs[s][r][c], B + (size_t)(col0 + r) * ldb + kb + c);
        }
        asm volatile("cp.async.commit_group;\n");
    }

    for (int kt = 0; kt < KT; kt++) {
        if (kt + 3 < KT) {
            int st = (kt + 3) & 3;
            int kb = (kt + 3) * TBK;
#pragma unroll
            for (int i = 0; i < 2; i++) {
                int v = tid + i * 128;
                int r = v >> 2, c = (v & 3) * 8;
                cpasync16(&As[st][r][c], A + (size_t)(row0 + r) * lda + kb + c);
                cpasync16(&Bs[st][r][c], B + (size_t)(col0 + r) * ldb + kb + c);
            }
        }
        asm volatile("cp.async.commit_group;\n");
        asm volatile("cp.async.wait_group 3;\n");
        __syncthreads();

        int st = kt & 3;
#pragma unroll
        for (int k16 = 0; k16 < 2; k16++) {
            uint32_t a[2][4], bb[2][4];
#pragma unroll
            for (int mt = 0; mt < 2; mt++) {
                uint32_t ad = (uint32_t)__cvta_generic_to_shared(
                    &As[st][wm * 32 + mt * 16 + (lane & 15)][k16 * 16 + (lane >> 4) * 8]);
                LDM4(a[mt][0], a[mt][1], a[mt][2], a[mt][3], ad);
            }
#pragma unroll
            for (int nt = 0; nt < 2; nt++) {
                uint32_t bd = (uint32_t)__cvta_generic_to_shared(
                    &Bs[st][wn * 32 + nt * 16 + (lane & 15)][k16 * 16 + (lane >> 4) * 8]);
                LDM4(bb[nt][0], bb[nt][1], bb[nt][2], bb[nt][3], bd);
            }
#pragma unroll
            for (int mt = 0; mt < 2; mt++)
#pragma unroll
                for (int nt = 0; nt < 2; nt++) {
                    MMA16816(acc[mt][nt * 2 + 0], a[mt], bb[nt][0], bb[nt][2]);
                    MMA16816(acc[mt][nt * 2 + 1], a[mt], bb[nt][1], bb[nt][3]);
                }
        }
        __syncthreads();
    }

#pragma unroll
    for (int mt = 0; mt < 2; mt++) {
        int r = row0 + wm * 32 + mt * 16 + (lane >> 2);
#pragma unroll
        for (int nj = 0; nj < 4; nj++) {
            int nt = nj >> 1, sub = nj & 1;
            int cb = col0 + wn * 32 + nt * 16 + sub * 8 + (lane & 3) * 2;
            float b0 = bias ? bias[cb] : 0.0f;
            float b1 = bias ? bias[cb + 1] : 0.0f;
            float* c4 = acc[mt][nj];
            C[(size_t)r * ldc + cb]           = c4[0] + b0;
            C[(size_t)r * ldc + cb + 1]       = c4[1] + b1;
            C[(size_t)(r + 8) * ldc + cb]     = c4[2] + b0;
            C[(size_t)(r + 8) * ldc + cb + 1] = c4[3] + b1;
        }
    }
}

// ------------------------- 128x128x32 GEMM, 256 threads (plain) ---------------
__global__ __launch_bounds__(256) void hgemm128(
    int M, int N, int K,
    const bf16* __restrict__ A, int lda,
    const bf16* __restrict__ B, int ldb,
    const float* __restrict__ bias,
    float* __restrict__ C, int ldc)
{
    __shared__ __align__(16) bf16 As[2][128][40];
    __shared__ __align__(16) bf16 Bs[2][128][40];

    int tid = threadIdx.x;
    int warp = tid >> 5, lane = tid & 31;
    int wm = warp >> 1, wn = warp & 1;
    int row0 = blockIdx.y * 128;
    int col0 = blockIdx.x * 128;

    float acc[2][8][4] = {};
    int KT = K / 32;

    {
#pragma unroll
        for (int i = 0; i < 2; i++) {
            int v = tid + i * 256;
            int r = v >> 2, c = (v & 3) * 8;
            cpasync16(&As[0][r][c], A + (size_t)(row0 + r) * lda + c);
            cpasync16(&Bs[0][r][c], B + (size_t)(col0 + r) * ldb + c);
        }
        asm volatile("cp.async.commit_group;\n");
    }

    for (int kt = 0; kt < KT; kt++) {
        if (kt + 1 < KT) {
            int st = (kt + 1) & 1;
            int kb = (kt + 1) * 32;
#pragma unroll
            for (int i = 0; i < 2; i++) {
                int v = tid + i * 256;
                int r = v >> 2, c = (v & 3) * 8;
                cpasync16(&As[st][r][c], A + (size_t)(row0 + r) * lda + kb + c);
                cpasync16(&Bs[st][r][c], B + (size_t)(col0 + r) * ldb + kb + c);
            }
            asm volatile("cp.async.commit_group;\n");
            asm volatile("cp.async.wait_group 1;\n");
        } else {
            asm volatile("cp.async.wait_group 0;\n");
        }
        __syncthreads();

        int st = kt & 1;
#pragma unroll
        for (int k16 = 0; k16 < 2; k16++) {
            uint32_t a[2][4], bb[4][4];
#pragma unroll
            for (int mt = 0; mt < 2; mt++) {
                uint32_t ad = (uint32_t)__cvta_generic_to_shared(
                    &As[st][wm * 32 + mt * 16 + (lane & 15)][k16 * 16 + (lane >> 4) * 8]);
                LDM4(a[mt][0], a[mt][1], a[mt][2], a[mt][3], ad);
            }
#pragma unroll
            for (int nt = 0; nt < 4; nt++) {
                uint32_t bd = (uint32_t)__cvta_generic_to_shared(
                    &Bs[st][wn * 64 + nt * 16 + (lane & 15)][k16 * 16 + (lane >> 4) * 8]);
                LDM4(bb[nt][0], bb[nt][1], bb[nt][2], bb[nt][3], bd);
            }
#pragma unroll
            for (int mt = 0; mt < 2; mt++)
#pragma unroll
                for (int nt = 0; nt < 4; nt++) {
                    MMA16816(acc[mt][nt * 2 + 0], a[mt], bb[nt][0], bb[nt][2]);
                    MMA16816(acc[mt][nt * 2 + 1], a[mt], bb[nt][1], bb[nt][3]);
                }
        }
        __syncthreads();
    }

#pragma unroll
    for (int mt = 0; mt < 2; mt++) {
        int r = row0 + wm * 32 + mt * 16 + (lane >> 2);
#pragma unroll
        for (int nf = 0; nf < 8; nf++) {
            int cb = col0 + wn * 64 + nf * 8 + (lane & 3) * 2;
            float b0 = bias ? bias[cb] : 0.0f;
            float b1 = bias ? bias[cb + 1] : 0.0f;
            float* c4 = acc[mt][nf];
            C[(size_t)r * ldc + cb]           = c4[0] + b0;
            C[(size_t)r * ldc + cb + 1]       = c4[1] + b1;
            C[(size_t)(r + 8) * ldc + cb]     = c4[2] + b0;
            C[(size_t)(r + 8) * ldc + cb + 1] = c4[3] + b1;
        }
    }
}

// ------------- logits GEMM: 128x256x32 tile, 3-stage, fused CE ----------------
// grid (NTILL, NROWS/128), 256 threads, dynamic SMEM.
#define LOGITS_SMEM ((128 * 40 + 256 * 40) * 3 * 2)

__global__ __launch_bounds__(256, 1) void hgemm_logits_ce(
    const bf16* __restrict__ A,   // [NROWS, NH]
    const bf16* __restrict__ B,   // [NV, NH]
    const float* __restrict__ bias,
    float2* __restrict__ cepart)  // [NTILL][NROWS] tile-major
{
    extern __shared__ __align__(16) bf16 dsm[];
    bf16* As = dsm;                     // [3][128][40]
    bf16* Bs = dsm + 3 * 128 * 40;      // [3][256][40]
    __shared__ float2 sred[4][128];

    int tid = threadIdx.x;
    int warp = tid >> 5, lane = tid & 31;
    int wm = warp >> 2, wn = warp & 3;        // 2x4 warps, 64x64 per warp
    int row0 = blockIdx.y * 128;
    int col0 = blockIdx.x * 256;

    float acc[4][8][4] = {};                  // [mt][nf][frag]
    const int KT = NH / 32;                   // 32

    // prologue: stages 0,1
#pragma unroll
    for (int s = 0; s < 2; s++) {
        int kb = s * 32;
#pragma unroll
        for (int i = 0; i < 2; i++) {
            int v = tid + i * 256;
            int r = v >> 2, c = (v & 3) * 8;
            cpasync16(As + ((s * 128 + r) * 40 + c),
                      A + (size_t)(row0 + r) * NH + kb + c);
        }
#pragma unroll
        for (int i = 0; i < 4; i++) {
            int v = tid + i * 256;
            int r = v >> 2, c = (v & 3) * 8;
            cpasync16(Bs + ((s * 256 + r) * 40 + c),
                      B + (size_t)(col0 + r) * NH + kb + c);
        }
        asm volatile("cp.async.commit_group;\n");
    }

    for (int kt = 0; kt < KT; kt++) {
        if (kt + 2 < KT) {
            int st = (kt + 2) % 3;
            int kb = (kt + 2) * 32;
#pragma unroll
            for (int i = 0; i < 2; i++) {
                int v = tid + i * 256;
                int r = v >> 2, c = (v & 3) * 8;
                cpasync16(As + ((st * 128 + r) * 40 + c),
                          A + (size_t)(row0 + r) * NH + kb + c);
            }
#pragma unroll
            for (int i = 0; i < 4; i++) {
                int v = tid + i * 256;
                int r = v >> 2, c = (v & 3) * 8;
                cpasync16(Bs + ((st * 256 + r) * 40 + c),
                          B + (size_t)(col0 + r) * NH + kb + c);
            }
        }
        asm volatile("cp.async.commit_group;\n");
        asm volatile("cp.async.wait_group 2;\n");
        __syncthreads();

        int st = kt % 3;
#pragma unroll
        for (int k16 = 0; k16 < 2; k16++) {
            uint32_t a[4][4], bb[4][4];
#pragma unroll
            for (int mt = 0; mt < 4; mt++) {
                uint32_t ad = (uint32_t)__cvta_generic_to_shared(
                    As + ((st * 128 + wm * 64 + mt * 16 + (lane & 15)) * 40 +
                          k16 * 16 + (lane >> 4) * 8));
                LDM4(a[mt][0], a[mt][1], a[mt][2], a[mt][3], ad);
            }
#pragma unroll
            for (int nt = 0; nt < 4; nt++) {
                uint32_t bd = (uint32_t)__cvta_generic_to_shared(
                    Bs + ((st * 256 + wn * 64 + nt * 16 + (lane & 15)) * 40 +
                          k16 * 16 + (lane >> 4) * 8));
                LDM4(bb[nt][0], bb[nt][1], bb[nt][2], bb[nt][3], bd);
            }
#pragma unroll
            for (int mt = 0; mt < 4; mt++)
#pragma unroll
                for (int nt = 0; nt < 4; nt++) {
                    MMA16816(acc[mt][nt * 2 + 0], a[mt], bb[nt][0], bb[nt][2]);
                    MMA16816(acc[mt][nt * 2 + 1], a[mt], bb[nt][1], bb[nt][3]);
                }
        }
        __syncthreads();
    }

    // fused CE epilogue: per-row online (max, sumexp) over this CTA's 256 cols
#pragma unroll
    for (int mt = 0; mt < 4; mt++) {
#pragma unroll
        for (int rs = 0; rs < 2; rs++) {
            int rl = wm * 64 + mt * 16 + rs * 8 + (lane >> 2);
            float m = -1e30f, s = 0.0f;
#pragma unroll
            for (int nf = 0; nf < 8; nf++) {
                int cb = col0 + wn * 64 + nf * 8 + (lane & 3) * 2;
                float v0 = acc[mt][nf][rs * 2 + 0] + bias[cb];
                float v1 = acc[mt][nf][rs * 2 + 1] + bias[cb + 1];
                if (v0 > m) { s = s * __expf(m - v0) + 1.0f; m = v0; }
                else        { s += __expf(v0 - m); }
                if (v1 > m) { s = s * __expf(m - v1) + 1.0f; m = v1; }
                else        { s += __expf(v1 - m); }
            }
#pragma unroll
            for (int off = 1; off <= 2; off <<= 1) {
                float mo = __shfl_xor_sync(0xffffffffu, m, off);
                float so = __shfl_xor_sync(0xffffffffu, s, off);
                float M = fmaxf(m, mo);
                s = s * __expf(m - M) + so * __expf(mo - M);
                m = M;
            }
            if ((lane & 3) == 0) sred[wn][rl] = make_float2(m, s);
        }
    }
    __syncthreads();
    if (tid < 128) {
        float2 p = sred[0][tid];
        float M = p.x, S = p.y;
#pragma unroll
        for (int w = 1; w < 4; w++) {
            float2 q = sred[w][tid];
            float Mn = fmaxf(M, q.x);
            S = S * __expf(M - Mn) + q.y * __expf(q.x - Mn);
            M = Mn;
        }
        cepart[(size_t)blockIdx.x * NROWS + row0 + tid] = make_float2(M, S);
    }
}

// ------------------------- GRU cells ------------------------------------------
__global__ __launch_bounds__(256) void gru_cell_enc(
    const float* __restrict__ gi_all, int t,
    const float* __restrict__ gh,
    float* __restrict__ hf, bf16* __restrict__ hb,
    const int* __restrict__ perm, const int* __restrict__ cnt,
    const int* __restrict__ lengths,
    float* __restrict__ context, bf16* __restrict__ context_b)
{
    int idx = blockIdx.x * blockDim.x + threadIdx.x;
    int i = idx >> 10;
    if (i >= cnt[t]) return;                 // batch finished: h frozen
    int j = idx & (NH - 1);
    int b = perm[i];
    const float* gib = gi_all + ((size_t)(b * NS + t)) * N3H;
    const float* ghb = gh + (size_t)i * N3H;
    float ir = gib[j], iz = gib[NH + j], in = gib[2 * NH + j];
    float hr = ghb[j], hz = ghb[NH + j], hn = ghb[2 * NH + j];
    float h = hf[idx];
    float r = sigmoidf_(ir + hr);
    float z = sigmoidf_(iz + hz);
    float n = tanhf(in + r * hn);
    float hv = (1.0f - z) * n + z * h;
    hf[idx] = hv;
    hb[idx] = __float2bfloat16(hv);
    if (t == lengths[b] - 1) {
        context[(size_t)b * NH + j] = hv;
        context_b[(size_t)b * NH + j] = __float2bfloat16(hv);
    }
}

__global__ __launch_bounds__(256) void gru_cell_dec(
    const float* __restrict__ gi_emb, const float* __restrict__ ctx_gi, int t,
    const float* __restrict__ gh,
    const float* __restrict__ h_old,
    float* __restrict__ h_new, bf16* __restrict__ hall_slot)
{
    int idx = blockIdx.x * blockDim.x + threadIdx.x;
    int b = idx >> 10;
    int j = idx & (NH - 1);
    const float* gib = gi_emb + ((size_t)(b * TD + t)) * N3H;
    const float* gcb = ctx_gi + b * N3H;
    const float* ghb = gh + b * N3H;
    float ir = gib[j] + gcb[j];
    float iz = gib[NH + j] + gcb[NH + j];
    float in = gib[2 * NH + j] + gcb[2 * NH + j];
    float hr = ghb[j], hz = ghb[NH + j], hn = ghb[2 * NH + j];
    float h = h_old[idx];
    float r = sigmoidf_(ir + hr);
    float z = sigmoidf_(iz + hz);
    float n = tanhf(in + r * hn);
    float hv = (1.0f - z) * n + z * h;
    h_new[idx] = hv;
    hall_slot[idx] = __float2bfloat16(hv);
}

// ------------------------- CE: target logit + reduce --------------------------
__global__ __launch_bounds__(256) void target_dot(
    const bf16* __restrict__ hall, const bf16* __restrict__ wfc,
    const float* __restrict__ bfc, const int* __restrict__ targets,
    float* __restrict__ tgt)
{
    int wid = (blockIdx.x * blockDim.x + threadIdx.x) >> 5;
    int lane = threadIdx.x & 31;
    if (wid >= NROWS) return;
    int t = wid / NB, b = wid % NB;
    int y = targets[b * NT + (t + 1)];
    const bf16* hrow = hall + (size_t)wid * NH;
    const bf16* wrow = wfc + (size_t)y * NH;
    float s = 0.0f;
    for (int k = lane; k < NH; k += 32)
        s = fmaf(__bfloat162float(hrow[k]), __bfloat162float(wrow[k]), s);
#pragma unroll
    for (int off = 16; off > 0; off >>= 1)
        s += __shfl_xor_sync(0xffffffffu, s, off);
    if (lane == 0) tgt[wid] = s + bfc[y];
}

__global__ __launch_bounds__(256) void ce_reduce(
    const float2* __restrict__ part, const float* __restrict__ tgt,
    const int* __restrict__ targets,
    float* __restrict__ ce, float* __restrict__ mask)
{
    int row = blockIdx.x * blockDim.x + threadIdx.x;
    if (row >= NROWS) return;
    float m = -1e30f, s = 0.0f;
    for (int i = 0; i < NTILL; i++) {
        float2 v = part[(size_t)i * NROWS + row];   // coalesced
        float M = fmaxf(m, v.x);
        s = s * __expf(m - M) + v.y * __expf(v.x - M);
        m = M;
    }
    float lse = m + logf(s);
    int t = row / NB, b = row % NB;
    int y = targets[b * NT + (t + 1)];
    ce[row] = lse - tgt[row];
    mask[row] = (y >= 1) ? 1.0f : 0.0f;
}

__global__ __launch_bounds__(256) void final_loss_kernel(
    const float* __restrict__ ce, const float* __restrict__ mask,
    float* __restrict__ out)
{
    __shared__ float s1[256], s2[256];
    int tid = threadIdx.x;
    float total = 0.0f;
    for (int t = 0; t < TD; t++) {
        s1[tid] = ce[t * NB + tid];
        s2[tid] = mask[t * NB + tid];
        __syncthreads();
        for (int off = 128; off > 0; off >>= 1) {
            if (tid < off) { s1[tid] += s1[tid + off]; s2[tid] += s2[tid + off]; }
            __syncthreads();
        }
        if (tid == 0) total += (s1[0] / (float)NB) * (s2[0] / (float)NB);
        __syncthreads();
    }
    if (tid == 0) out[0] = total / (float)NT;
}

// ------------------------- host orchestration ---------------------------------
extern "C" void kernel_launch(void* const* d_in, const int* in_sizes, int n_in,
                              void* d_out, int out_size)
{
    const int*   inputs  = (const int*)d_in[0];
    const int*   targets = (const int*)d_in[1];
    const int*   lengths = (const int*)d_in[2];
    const float* h0_enc  = (const float*)d_in[3];
    const float* E_enc   = (const float*)d_in[4];
    const float* E_dec   = (const float*)d_in[5];
    const float* W_ih_e  = (const float*)d_in[6];
    const float* W_hh_e  = (const float*)d_in[7];
    const float* b_ih_e  = (const float*)d_in[8];
    const float* b_hh_e  = (const float*)d_in[9];
    const float* W_ih_d  = (const float*)d_in[10];
    const float* W_hh_d  = (const float*)d_in[11];
    const float* b_ih_d  = (const float*)d_in[12];
    const float* b_hh_d  = (const float*)d_in[13];
    const float* W_fc    = (const float*)d_in[14];
    const float* b_fc    = (const float*)d_in[15];
    float* out = (float*)d_out;

    float *p_gienc, *p_gh, *p_hf, *p_hd, *p_ctx, *p_ctxgi, *p_gidec, *p_tgt,
          *p_ce, *p_mask;
    float2* p_cepart;
    int *p_perm, *p_cnt;
    bf16 *p_embb, *p_dembb, *p_hb0, *p_ctxb, *p_hall;
    bf16 *p_whe, *p_whd, *p_wfc, *p_wie, *p_wide, *p_widc;
    cudaGetSymbolAddress((void**)&p_gienc,  g_gi_enc);
    cudaGetSymbolAddress((void**)&p_gh,     g_gh);
    cudaGetSymbolAddress((void**)&p_hf,     g_hf);
    cudaGetSymbolAddress((void**)&p_hd,     g_hd);
    cudaGetSymbolAddress((void**)&p_ctx,    g_ctx);
    cudaGetSymbolAddress((void**)&p_ctxgi,  g_ctxgi);
    cudaGetSymbolAddress((void**)&p_gidec,  g_gidec);
    cudaGetSymbolAddress((void**)&p_cepart, g_cepart);
    cudaGetSymbolAddress((void**)&p_tgt,    g_tgt);
    cudaGetSymbolAddress((void**)&p_ce,     g_ce);
    cudaGetSymbolAddress((void**)&p_mask,   g_mask);
    cudaGetSymbolAddress((void**)&p_perm,   g_perm);
    cudaGetSymbolAddress((void**)&p_cnt,    g_cnt);
    cudaGetSymbolAddress((void**)&p_embb,   g_embb);
    cudaGetSymbolAddress((void**)&p_dembb,  g_dembb);
    cudaGetSymbolAddress((void**)&p_hb0,    g_hb0);
    cudaGetSymbolAddress((void**)&p_ctxb,   g_ctxb);
    cudaGetSymbolAddress((void**)&p_hall,   g_hall);
    cudaGetSymbolAddress((void**)&p_whe,    wb_hh_e);
    cudaGetSymbolAddress((void**)&p_whd,    wb_hh_d);
    cudaGetSymbolAddress((void**)&p_wfc,    wb_fc);
    cudaGetSymbolAddress((void**)&p_wie,    wb_ih_e);
    cudaGetSymbolAddress((void**)&p_wide,   wb_ihd_emb);
    cudaGetSymbolAddress((void**)&p_widc,   wb_ihd_ctx);

    cudaFuncSetAttribute(hgemm_logits_ce,
                         cudaFuncAttributeMaxDynamicSharedMemorySize,
                         LOGITS_SMEM);

    static cudaStream_t s2 = nullptr;
    static cudaEvent_t ev_fork = nullptr, ev_join = nullptr;
    if (s2 == nullptr) {
        cudaStreamCreate(&s2);
        cudaEventCreateWithFlags(&ev_fork, cudaEventDisableTiming);
        cudaEventCreateWithFlags(&ev_join, cudaEventDisableTiming);
    }

    // ---- fork: decoder-side prep runs concurrently with encoder ----
    cudaEventRecord(ev_fork, 0);
    cudaStreamWaitEvent(s2, ev_fork, 0);

    f2bf<<<2048, 256, 0, s2>>>(W_fc, p_wfc, NV * NH);
    f2bf<<<512, 256, 0, s2>>>(W_hh_d, p_whd, N3H * NH);
    f2bf_slice<<<256, 256, 0, s2>>>(W_ih_d, NE + NH, 0, NE, p_wide, NEP, N3H);
    gather_demb_bf<<<256, 256, 0, s2>>>(targets, E_dec, p_dembb);
    {
        dim3 grid(N3H / 128, NROWS / 128);       // 24 x 38
        hgemm128<<<grid, 256, 0, s2>>>(NROWS, N3H, NEP, p_dembb, NEP,
                                       p_wide, NEP, nullptr, p_gidec, N3H);
    }
    cudaEventRecord(ev_join, s2);

    // main stream: encoder-side prep
    f2bf<<<512, 256>>>(W_hh_e, p_whe, N3H * NH);
    f2bf_slice<<<256, 256>>>(W_ih_e, NE, 0, NE, p_wie, NEP, N3H);
    f2bf_slice<<<512, 256>>>(W_ih_d, NE + NH, NE, NH, p_widc, NH, N3H);
    build_perm<<<1, NB>>>(lengths, p_perm, p_cnt);
    permute_h0<<<BH / 256, 256>>>(h0_enc, p_perm, p_hf, p_hb0);
    gather_emb_enc_bf<<<512, 256>>>(inputs, E_enc, p_embb);

    // ---- encoder input-side gates ----
    {
        dim3 grid(N3H / 128, (NB * NS) / 128);   // 24 x 128
        hgemm128<<<grid, 256>>>(NB * NS, N3H, NEP, p_embb, NEP, p_wie, NEP,
                                b_ih_e, p_gienc, N3H);
    }

    // ---- encoder recurrence (length-sorted, shrinking active set) ----
    dim3 grid_rec(N3H / TBN, NB / TBM);          // 48 x 4
    for (int t = 0; t < NS; t++) {
        hgemm<<<grid_rec, 128>>>(NB, N3H, NH, p_hb0, NH, p_whe, NH,
                                 b_hh_e, p_gh, N3H, p_cnt, t);
        gru_cell_enc<<<BH / 256, 256>>>(p_gienc, t, p_gh, p_hf, p_hb0,
                                        p_perm, p_cnt, lengths, p_ctx, p_ctxb);
    }

    // ---- decoder prologue ----
    hgemm<<<grid_rec, 128>>>(NB, N3H, NH, p_ctxb, NH, p_widc, NH,
                             b_ih_d, p_ctxgi, N3H, nullptr, 0);

    cudaStreamWaitEvent(0, ev_join, 0);

    // ---- decoder recurrence ----
    for (int t = 0; t < TD; t++) {
        const float* hp = (t == 0) ? p_ctx : p_hd;
        const bf16* hpb = (t == 0) ? p_ctxb : (p_hall + (size_t)(t - 1) * BH);
        hgemm<<<grid_rec, 128>>>(NB, N3H, NH, hpb, NH, p_whd, NH,
                                 b_hh_d, p_gh, N3H, nullptr, 0);
        gru_cell_dec<<<BH / 256, 256>>>(p_gidec, p_ctxgi, t, p_gh, hp, p_hd,
                                        p_hall + (size_t)t * BH);
    }

    // ---- logits GEMM (128x256 tiles) with fused CE partials ----
    {
        dim3 grid(NTILL, NROWS / 128);           // 125 x 38
        hgemm_logits_ce<<<grid, 256, LOGITS_SMEM>>>(p_hall, p_wfc, b_fc,
                                                    p_cepart);
    }

    // ---- CE finish ----
    target_dot<<<(NROWS * 32 + 255) / 256, 256>>>(p_hall, p_wfc, b_fc, targets, p_tgt);
    ce_reduce<<<(NROWS + 255) / 256, 256>>>(p_cepart, p_tgt, targets, p_ce, p_mask);
    final_loss_kernel<<<1, 256>>>(p_ce, p_mask, out);
}

// round 9
// speedup vs baseline: 1.0398x; 1.0398x over previous
#include <cuda_runtime.h>
#include <cuda_bf16.h>
#include <math.h>
#include <stdint.h>

#define NB 256
#define NS 64
#define NT 20
#define NE 100
#define NEP 128
#define NH 1024
#define NV 32000
#define N3H (3 * NH)
#define TD (NT - 1)
#define BH (NB * NH)
#define NROWS (NB * TD)       // 4864 decoder rows
#define NTILN (NV / 128)      // 250 col tiles of logits

typedef __nv_bfloat16 bf16;

// ------------------------- scratch (device globals) -------------------------
__device__ float g_gi_enc[(size_t)NB * NS * N3H];   // 201 MB
__device__ float g_gh[NB * N3H];
__device__ float g_hf[BH];
__device__ float g_hd[BH];
__device__ float g_ctx[BH];
__device__ float g_ctxgi[NB * N3H];
__device__ float g_gidec[(size_t)NROWS * N3H];      // 60 MB
__device__ float2 g_cepart[(size_t)NROWS * NTILN];  // 9.7 MB
__device__ float g_tgt[NROWS];
__device__ float g_ce[NROWS];
__device__ float g_mask[NROWS];
__device__ int g_perm[NB];
__device__ int g_cnt[NS];

__device__ bf16 g_embb[(size_t)NB * NS * NEP];
__device__ bf16 g_dembb[(size_t)NROWS * NEP];
__device__ bf16 g_hb0[BH];
__device__ bf16 g_ctxb[BH];
__device__ bf16 g_hall[(size_t)TD * BH];
__device__ bf16 wb_hh_e[(size_t)N3H * NH];
__device__ bf16 wb_hh_d[(size_t)N3H * NH];
__device__ bf16 wb_fc[(size_t)NV * NH];
__device__ bf16 wb_ih_e[(size_t)N3H * NEP];
__device__ bf16 wb_ihd_emb[(size_t)N3H * NEP];
__device__ bf16 wb_ihd_ctx[(size_t)N3H * NH];

// ------------------------- helpers -------------------------------------------
__device__ __forceinline__ void cpasync16(void* smem, const void* gmem)
{
    uint32_t s = (uint32_t)__cvta_generic_to_shared(smem);
    asm volatile("cp.async.cg.shared.global [%0], [%1], 16;\n" ::"r"(s), "l"(gmem));
}

#define LDM4(r0, r1, r2, r3, smaddr)                                            \
    asm volatile("ldmatrix.sync.aligned.m8n8.x4.shared.b16 {%0,%1,%2,%3}, [%4];" \
                 : "=r"(r0), "=r"(r1), "=r"(r2), "=r"(r3) : "r"(smaddr))

#define MMA16816(c, a, b0, b1)                                                   \
    asm volatile("mma.sync.aligned.m16n8k16.row.col.f32.bf16.bf16.f32 "          \
                 "{%0,%1,%2,%3}, {%4,%5,%6,%7}, {%8,%9}, {%0,%1,%2,%3};"         \
                 : "+f"(c[0]), "+f"(c[1]), "+f"(c[2]), "+f"(c[3])                \
                 : "r"(a[0]), "r"(a[1]), "r"(a[2]), "r"(a[3]), "r"(b0), "r"(b1))

__device__ __forceinline__ float sigmoidf_(float x) {
    return 1.0f / (1.0f + __expf(-x));
}

// ------------------------- conversions / gathers ------------------------------
__global__ __launch_bounds__(256) void f2bf(const float* __restrict__ in,
                                            bf16* __restrict__ out, int n)
{
    for (int i = blockIdx.x * blockDim.x + threadIdx.x; i < n;
         i += gridDim.x * blockDim.x)
        out[i] = __float2bfloat16(in[i]);
}

__global__ __launch_bounds__(256) void f2bf_slice(
    const float* __restrict__ in, int ldin, int koff, int kin,
    bf16* __restrict__ out, int kout, int rows)
{
    int n = rows * kout;
    for (int i = blockIdx.x * blockDim.x + threadIdx.x; i < n;
         i += gridDim.x * blockDim.x) {
        int r = i / kout, c = i % kout;
        out[i] = (c < kin) ? __float2bfloat16(in[(size_t)r * ldin + koff + c])
                           : __float2bfloat16(0.0f);
    }
}

__global__ __launch_bounds__(256) void gather_emb_enc_bf(
    const int* __restrict__ tokens, const float* __restrict__ table,
    bf16* __restrict__ out)
{
    int n = NB * NS * NEP;
    for (int i = blockIdx.x * blockDim.x + threadIdx.x; i < n;
         i += gridDim.x * blockDim.x) {
        int c = i % NEP, m = i / NEP;
        float v = 0.0f;
        if (c < NE) v = table[tokens[m] * NE + c];
        out[i] = __float2bfloat16(v);
    }
}

__global__ __launch_bounds__(256) void gather_demb_bf(
    const int* __restrict__ targets, const float* __restrict__ E_dec,
    bf16* __restrict__ out)
{
    int n = NROWS * NEP;
    for (int i = blockIdx.x * blockDim.x + threadIdx.x; i < n;
         i += gridDim.x * blockDim.x) {
        int c = i % NEP, m = i / NEP;
        int t = m % TD, b = m / TD;
        float v = 0.0f;
        if (c < NE) {
            int tok = (t == 0) ? 1 : targets[b * NT + t];
            v = E_dec[tok * NE + c];
        }
        out[i] = __float2bfloat16(v);
    }
}

// ---- batch permutation sorted by length (desc), cnt[t] = #{len >= t+1} ------
__global__ __launch_bounds__(NB) void build_perm(
    const int* __restrict__ lengths, int* __restrict__ perm,
    int* __restrict__ cnt)
{
    __shared__ int slen[NB];
    int tid = threadIdx.x;
    slen[tid] = lengths[tid];
    __syncthreads();
    int L = slen[tid];
    int rank = 0;
    for (int i = 0; i < NB; i++) {
        int Li = slen[i];
        if (Li > L || (Li == L && i < tid)) rank++;
    }
    perm[rank] = tid;
    if (tid < NS) {
        int c = 0;
        for (int i = 0; i < NB; i++) c += (slen[i] >= tid + 1);
        cnt[tid] = c;
    }
}

__global__ __launch_bounds__(256) void permute_h0(
    const float* __restrict__ h0, const int* __restrict__ perm,
    float* __restrict__ hf, bf16* __restrict__ hb)
{
    int idx = blockIdx.x * blockDim.x + threadIdx.x;
    int i = idx >> 10, j = idx & (NH - 1);
    float v = h0[(size_t)perm[i] * NH + j];
    hf[idx] = v;
    hb[idx] = __float2bfloat16(v);
}

// ------------- 64x64x32 GEMM, 4-stage cp.async pipeline (recurrence) ----------
#define TBM 64
#define TBN 64
#define TBK 32

__global__ __launch_bounds__(128) void hgemm(
    int M, int N, int K,
    const bf16* __restrict__ A, int lda,
    const bf16* __restrict__ B, int ldb,
    const float* __restrict__ bias,
    float* __restrict__ C, int ldc,
    const int* __restrict__ cnt, int t)
{
    __shared__ __align__(16) bf16 As[4][TBM][40];
    __shared__ __align__(16) bf16 Bs[4][TBN][40];

    int row0 = blockIdx.y * TBM;
    if (cnt != nullptr && row0 >= cnt[t]) return;   // length-sorted early exit

    int tid = threadIdx.x;
    int warp = tid >> 5, lane = tid & 31;
    int wm = warp >> 1, wn = warp & 1;
    int col0 = blockIdx.x * TBN;

    float acc[2][4][4] = {};
    int KT = K / TBK;

#pragma unroll
    for (int s = 0; s < 3; s++) {
        int kb = s * TBK;
#pragma unroll
        for (int i = 0; i < 2; i++) {
            int v = tid + i * 128;
            int r = v >> 2, c = (v & 3) * 8;
            cpasync16(&As[s][r][c], A + (size_t)(row0 + r) * lda + kb + c);
            cpasync16(&Bs[s][r][c], B + (size_t)(col0 + r) * ldb + kb + c);
        }
        asm volatile("cp.async.commit_group;\n");
    }

    for (int kt = 0; kt < KT; kt++) {
        if (kt + 3 < KT) {
            int st = (kt + 3) & 3;
            int kb = (kt + 3) * TBK;
#pragma unroll
            for (int i = 0; i < 2; i++) {
                int v = tid + i * 128;
                int r = v >> 2, c = (v & 3) * 8;
                cpasync16(&As[st][r][c], A + (size_t)(row0 + r) * lda + kb + c);
                cpasync16(&Bs[st][r][c], B + (size_t)(col0 + r) * ldb + kb + c);
            }
        }
        asm volatile("cp.async.commit_group;\n");
        asm volatile("cp.async.wait_group 3;\n");
        __syncthreads();

        int st = kt & 3;
#pragma unroll
        for (int k16 = 0; k16 < 2; k16++) {
            uint32_t a[2][4], bb[2][4];
#pragma unroll
            for (int mt = 0; mt < 2; mt++) {
                uint32_t ad = (uint32_t)__cvta_generic_to_shared(
                    &As[st][wm * 32 + mt * 16 + (lane & 15)][k16 * 16 + (lane >> 4) * 8]);
                LDM4(a[mt][0], a[mt][1], a[mt][2], a[mt][3], ad);
            }
#pragma unroll
            for (int nt = 0; nt < 2; nt++) {
                uint32_t bd = (uint32_t)__cvta_generic_to_shared(
                    &Bs[st][wn * 32 + nt * 16 + (lane & 15)][k16 * 16 + (lane >> 4) * 8]);
                LDM4(bb[nt][0], bb[nt][1], bb[nt][2], bb[nt][3], bd);
            }
#pragma unroll
            for (int mt = 0; mt < 2; mt++)
#pragma unroll
                for (int nt = 0; nt < 2; nt++) {
                    MMA16816(acc[mt][nt * 2 + 0], a[mt], bb[nt][0], bb[nt][2]);
                    MMA16816(acc[mt][nt * 2 + 1], a[mt], bb[nt][1], bb[nt][3]);
                }
        }
        __syncthreads();
    }

#pragma unroll
    for (int mt = 0; mt < 2; mt++) {
        int r = row0 + wm * 32 + mt * 16 + (lane >> 2);
#pragma unroll
        for (int nj = 0; nj < 4; nj++) {
            int nt = nj >> 1, sub = nj & 1;
            int cb = col0 + wn * 32 + nt * 16 + sub * 8 + (lane & 3) * 2;
            float b0 = bias ? bias[cb] : 0.0f;
            float b1 = bias ? bias[cb + 1] : 0.0f;
            float* c4 = acc[mt][nj];
            C[(size_t)r * ldc + cb]           = c4[0] + b0;
            C[(size_t)r * ldc + cb + 1]       = c4[1] + b1;
            C[(size_t)(r + 8) * ldc + cb]     = c4[2] + b0;
            C[(size_t)(r + 8) * ldc + cb + 1] = c4[3] + b1;
        }
    }
}

// ------------------------- 128x128x32 GEMM, 256 threads -----------------------
// CE=1: per-row (max,sumexp) partials into cepart instead of writing C.
// row_base: global row offset of this launch (for chunked logits).
template <int CE>
__global__ __launch_bounds__(256) void hgemm128(
    int M, int N, int K,
    const bf16* __restrict__ A, int lda,
    const bf16* __restrict__ B, int ldb,
    const float* __restrict__ bias,
    float* __restrict__ C, int ldc,
    float2* __restrict__ cepart, int row_base)
{
    __shared__ __align__(16) bf16 As[2][128][40];
    __shared__ __align__(16) bf16 Bs[2][128][40];
    __shared__ float2 sred[2][128];

    int tid = threadIdx.x;
    int warp = tid >> 5, lane = tid & 31;
    int wm = warp >> 1, wn = warp & 1;
    int row0 = row_base + blockIdx.y * 128;
    int col0 = blockIdx.x * 128;

    float acc[2][8][4] = {};
    int KT = K / 32;

    {
#pragma unroll
        for (int i = 0; i < 2; i++) {
            int v = tid + i * 256;
            int r = v >> 2, c = (v & 3) * 8;
            cpasync16(&As[0][r][c], A + (size_t)(row0 + r) * lda + c);
            cpasync16(&Bs[0][r][c], B + (size_t)(col0 + r) * ldb + c);
        }
        asm volatile("cp.async.commit_group;\n");
    }

    for (int kt = 0; kt < KT; kt++) {
        if (kt + 1 < KT) {
            int st = (kt + 1) & 1;
            int kb = (kt + 1) * 32;
#pragma unroll
            for (int i = 0; i < 2; i++) {
                int v = tid + i * 256;
                int r = v >> 2, c = (v & 3) * 8;
                cpasync16(&As[st][r][c], A + (size_t)(row0 + r) * lda + kb + c);
                cpasync16(&Bs[st][r][c], B + (size_t)(col0 + r) * ldb + kb + c);
            }
            asm volatile("cp.async.commit_group;\n");
            asm volatile("cp.async.wait_group 1;\n");
        } else {
            asm volatile("cp.async.wait_group 0;\n");
        }
        __syncthreads();

        int st = kt & 1;
#pragma unroll
        for (int k16 = 0; k16 < 2; k16++) {
            uint32_t a[2][4], bb[4][4];
#pragma unroll
            for (int mt = 0; mt < 2; mt++) {
                uint32_t ad = (uint32_t)__cvta_generic_to_shared(
                    &As[st][wm * 32 + mt * 16 + (lane & 15)][k16 * 16 + (lane >> 4) * 8]);
                LDM4(a[mt][0], a[mt][1], a[mt][2], a[mt][3], ad);
            }
#pragma unroll
            for (int nt = 0; nt < 4; nt++) {
                uint32_t bd = (uint32_t)__cvta_generic_to_shared(
                    &Bs[st][wn * 64 + nt * 16 + (lane & 15)][k16 * 16 + (lane >> 4) * 8]);
                LDM4(bb[nt][0], bb[nt][1], bb[nt][2], bb[nt][3], bd);
            }
#pragma unroll
            for (int mt = 0; mt < 2; mt++)
#pragma unroll
                for (int nt = 0; nt < 4; nt++) {
                    MMA16816(acc[mt][nt * 2 + 0], a[mt], bb[nt][0], bb[nt][2]);
                    MMA16816(acc[mt][nt * 2 + 1], a[mt], bb[nt][1], bb[nt][3]);
                }
        }
        __syncthreads();
    }

    if (CE == 0) {
#pragma unroll
        for (int mt = 0; mt < 2; mt++) {
            int r = row0 + wm * 32 + mt * 16 + (lane >> 2);
#pragma unroll
            for (int nf = 0; nf < 8; nf++) {
                int cb = col0 + wn * 64 + nf * 8 + (lane & 3) * 2;
                float b0 = bias ? bias[cb] : 0.0f;
                float b1 = bias ? bias[cb + 1] : 0.0f;
                float* c4 = acc[mt][nf];
                C[(size_t)r * ldc + cb]           = c4[0] + b0;
                C[(size_t)r * ldc + cb + 1]       = c4[1] + b1;
                C[(size_t)(r + 8) * ldc + cb]     = c4[2] + b0;
                C[(size_t)(r + 8) * ldc + cb + 1] = c4[3] + b1;
            }
        }
    } else {
#pragma unroll
        for (int mt = 0; mt < 2; mt++) {
#pragma unroll
            for (int rs = 0; rs < 2; rs++) {
                int rl = wm * 32 + mt * 16 + rs * 8 + (lane >> 2);
                float m = -1e30f, s = 0.0f;
#pragma unroll
                for (int nf = 0; nf < 8; nf++) {
                    int cb = col0 + wn * 64 + nf * 8 + (lane & 3) * 2;
                    float v0 = acc[mt][nf][rs * 2 + 0] + bias[cb];
                    float v1 = acc[mt][nf][rs * 2 + 1] + bias[cb + 1];
                    if (v0 > m) { s = s * __expf(m - v0) + 1.0f; m = v0; }
                    else        { s += __expf(v0 - m); }
                    if (v1 > m) { s = s * __expf(m - v1) + 1.0f; m = v1; }
                    else        { s += __expf(v1 - m); }
                }
#pragma unroll
                for (int off = 1; off <= 2; off <<= 1) {
                    float mo = __shfl_xor_sync(0xffffffffu, m, off);
                    float so = __shfl_xor_sync(0xffffffffu, s, off);
                    float M = fmaxf(m, mo);
                    s = s * __expf(m - M) + so * __expf(mo - M);
                    m = M;
                }
                if ((lane & 3) == 0) sred[wn][rl] = make_float2(m, s);
            }
        }
        __syncthreads();
        if (tid < 128) {
            float2 p0 = sred[0][tid], p1 = sred[1][tid];
            float M = fmaxf(p0.x, p1.x);
            float S = p0.y * __expf(p0.x - M) + p1.y * __expf(p1.x - M);
            cepart[(size_t)(row0 + tid) * NTILN + blockIdx.x] = make_float2(M, S);
        }
    }
}

// ------------------------- GRU cells ------------------------------------------
__global__ __launch_bounds__(256) void gru_cell_enc(
    const float* __restrict__ gi_all, int t,
    const float* __restrict__ gh,
    float* __restrict__ hf, bf16* __restrict__ hb,
    const int* __restrict__ perm, const int* __restrict__ cnt,
    const int* __restrict__ lengths,
    float* __restrict__ context, bf16* __restrict__ context_b)
{
    int idx = blockIdx.x * blockDim.x + threadIdx.x;
    int i = idx >> 10;
    if (i >= cnt[t]) return;
    int j = idx & (NH - 1);
    int b = perm[i];
    const float* gib = gi_all + ((size_t)(b * NS + t)) * N3H;
    const float* ghb = gh + (size_t)i * N3H;
    float ir = gib[j], iz = gib[NH + j], in = gib[2 * NH + j];
    float hr = ghb[j], hz = ghb[NH + j], hn = ghb[2 * NH + j];
    float h = hf[idx];
    float r = sigmoidf_(ir + hr);
    float z = sigmoidf_(iz + hz);
    float n = tanhf(in + r * hn);
    float hv = (1.0f - z) * n + z * h;
    hf[idx] = hv;
    hb[idx] = __float2bfloat16(hv);
    if (t == lengths[b] - 1) {
        context[(size_t)b * NH + j] = hv;
        context_b[(size_t)b * NH + j] = __float2bfloat16(hv);
    }
}

__global__ __launch_bounds__(256) void gru_cell_dec(
    const float* __restrict__ gi_emb, const float* __restrict__ ctx_gi, int t,
    const float* __restrict__ gh,
    const float* __restrict__ h_old,
    float* __restrict__ h_new, bf16* __restrict__ hall_slot)
{
    int idx = blockIdx.x * blockDim.x + threadIdx.x;
    int b = idx >> 10;
    int j = idx & (NH - 1);
    const float* gib = gi_emb + ((size_t)(b * TD + t)) * N3H;
    const float* gcb = ctx_gi + b * N3H;
    const float* ghb = gh + b * N3H;
    float ir = gib[j] + gcb[j];
    float iz = gib[NH + j] + gcb[NH + j];
    float in = gib[2 * NH + j] + gcb[2 * NH + j];
    float hr = ghb[j], hz = ghb[NH + j], hn = ghb[2 * NH + j];
    float h = h_old[idx];
    float r = sigmoidf_(ir + hr);
    float z = sigmoidf_(iz + hz);
    float n = tanhf(in + r * hn);
    float hv = (1.0f - z) * n + z * h;
    h_new[idx] = hv;
    hall_slot[idx] = __float2bfloat16(hv);
}

// ------------------------- CE: target logit + reduce --------------------------
__global__ __launch_bounds__(256) void target_dot(
    const bf16* __restrict__ hall, const bf16* __restrict__ wfc,
    const float* __restrict__ bfc, const int* __restrict__ targets,
    float* __restrict__ tgt)
{
    int wid = (blockIdx.x * blockDim.x + threadIdx.x) >> 5;
    int lane = threadIdx.x & 31;
    if (wid >= NROWS) return;
    int t = wid / NB, b = wid % NB;
    int y = targets[b * NT + (t + 1)];
    const bf16* hrow = hall + (size_t)wid * NH;
    const bf16* wrow = wfc + (size_t)y * NH;
    float s = 0.0f;
    for (int k = lane; k < NH; k += 32)
        s = fmaf(__bfloat162float(hrow[k]), __bfloat162float(wrow[k]), s);
#pragma unroll
    for (int off = 16; off > 0; off >>= 1)
        s += __shfl_xor_sync(0xffffffffu, s, off);
    if (lane == 0) tgt[wid] = s + bfc[y];
}

__global__ __launch_bounds__(256) void ce_reduce(
    const float2* __restrict__ part, const float* __restrict__ tgt,
    const int* __restrict__ targets,
    float* __restrict__ ce, float* __restrict__ mask)
{
    int row = blockIdx.x * blockDim.x + threadIdx.x;
    if (row >= NROWS) return;
    float m = -1e30f, s = 0.0f;
    const float2* p = part + (size_t)row * NTILN;
    for (int i = 0; i < NTILN; i++) {
        float2 v = p[i];
        float M = fmaxf(m, v.x);
        s = s * __expf(m - M) + v.y * __expf(v.x - M);
        m = M;
    }
    float lse = m + logf(s);
    int t = row / NB, b = row % NB;
    int y = targets[b * NT + (t + 1)];
    ce[row] = lse - tgt[row];
    mask[row] = (y >= 1) ? 1.0f : 0.0f;
}

__global__ __launch_bounds__(256) void final_loss_kernel(
    const float* __restrict__ ce, const float* __restrict__ mask,
    float* __restrict__ out)
{
    __shared__ float s1[256], s2[256];
    int tid = threadIdx.x;
    float total = 0.0f;
    for (int t = 0; t < TD; t++) {
        s1[tid] = ce[t * NB + tid];
        s2[tid] = mask[t * NB + tid];
        __syncthreads();
        for (int off = 128; off > 0; off >>= 1) {
            if (tid < off) { s1[tid] += s1[tid + off]; s2[tid] += s2[tid + off]; }
            __syncthreads();
        }
        if (tid == 0) total += (s1[0] / (float)NB) * (s2[0] / (float)NB);
        __syncthreads();
    }
    if (tid == 0) out[0] = total / (float)NT;
}

// ------------------------- host orchestration ---------------------------------
extern "C" void kernel_launch(void* const* d_in, const int* in_sizes, int n_in,
                              void* d_out, int out_size)
{
    const int*   inputs  = (const int*)d_in[0];
    const int*   targets = (const int*)d_in[1];
    const int*   lengths = (const int*)d_in[2];
    const float* h0_enc  = (const float*)d_in[3];
    const float* E_enc   = (const float*)d_in[4];
    const float* E_dec   = (const float*)d_in[5];
    const float* W_ih_e  = (const float*)d_in[6];
    const float* W_hh_e  = (const float*)d_in[7];
    const float* b_ih_e  = (const float*)d_in[8];
    const float* b_hh_e  = (const float*)d_in[9];
    const float* W_ih_d  = (const float*)d_in[10];
    const float* W_hh_d  = (const float*)d_in[11];
    const float* b_ih_d  = (const float*)d_in[12];
    const float* b_hh_d  = (const float*)d_in[13];
    const float* W_fc    = (const float*)d_in[14];
    const float* b_fc    = (const float*)d_in[15];
    float* out = (float*)d_out;

    float *p_gienc, *p_gh, *p_hf, *p_hd, *p_ctx, *p_ctxgi, *p_gidec, *p_tgt,
          *p_ce, *p_mask;
    float2* p_cepart;
    int *p_perm, *p_cnt;
    bf16 *p_embb, *p_dembb, *p_hb0, *p_ctxb, *p_hall;
    bf16 *p_whe, *p_whd, *p_wfc, *p_wie, *p_wide, *p_widc;
    cudaGetSymbolAddress((void**)&p_gienc,  g_gi_enc);
    cudaGetSymbolAddress((void**)&p_gh,     g_gh);
    cudaGetSymbolAddress((void**)&p_hf,     g_hf);
    cudaGetSymbolAddress((void**)&p_hd,     g_hd);
    cudaGetSymbolAddress((void**)&p_ctx,    g_ctx);
    cudaGetSymbolAddress((void**)&p_ctxgi,  g_ctxgi);
    cudaGetSymbolAddress((void**)&p_gidec,  g_gidec);
    cudaGetSymbolAddress((void**)&p_cepart, g_cepart);
    cudaGetSymbolAddress((void**)&p_tgt,    g_tgt);
    cudaGetSymbolAddress((void**)&p_ce,     g_ce);
    cudaGetSymbolAddress((void**)&p_mask,   g_mask);
    cudaGetSymbolAddress((void**)&p_perm,   g_perm);
    cudaGetSymbolAddress((void**)&p_cnt,    g_cnt);
    cudaGetSymbolAddress((void**)&p_embb,   g_embb);
    cudaGetSymbolAddress((void**)&p_dembb,  g_dembb);
    cudaGetSymbolAddress((void**)&p_hb0,    g_hb0);
    cudaGetSymbolAddress((void**)&p_ctxb,   g_ctxb);
    cudaGetSymbolAddress((void**)&p_hall,   g_hall);
    cudaGetSymbolAddress((void**)&p_whe,    wb_hh_e);
    cudaGetSymbolAddress((void**)&p_whd,    wb_hh_d);
    cudaGetSymbolAddress((void**)&p_wfc,    wb_fc);
    cudaGetSymbolAddress((void**)&p_wie,    wb_ih_e);
    cudaGetSymbolAddress((void**)&p_wide,   wb_ihd_emb);
    cudaGetSymbolAddress((void**)&p_widc,   wb_ihd_ctx);

    static cudaStream_t s2 = nullptr;
    static cudaEvent_t ev_fork = nullptr, ev_join = nullptr, ev_step = nullptr,
                       ev_log = nullptr;
    if (s2 == nullptr) {
        cudaStreamCreate(&s2);
        cudaEventCreateWithFlags(&ev_fork, cudaEventDisableTiming);
        cudaEventCreateWithFlags(&ev_join, cudaEventDisableTiming);
        cudaEventCreateWithFlags(&ev_step, cudaEventDisableTiming);
        cudaEventCreateWithFlags(&ev_log, cudaEventDisableTiming);
    }

    // ---- fork: decoder-side prep runs concurrently with encoder ----
    cudaEventRecord(ev_fork, 0);
    cudaStreamWaitEvent(s2, ev_fork, 0);

    f2bf<<<2048, 256, 0, s2>>>(W_fc, p_wfc, NV * NH);
    f2bf<<<512, 256, 0, s2>>>(W_hh_d, p_whd, N3H * NH);
    f2bf_slice<<<256, 256, 0, s2>>>(W_ih_d, NE + NH, 0, NE, p_wide, NEP, N3H);
    gather_demb_bf<<<256, 256, 0, s2>>>(targets, E_dec, p_dembb);
    {
        dim3 grid(N3H / 128, NROWS / 128);       // 24 x 38
        hgemm128<0><<<grid, 256, 0, s2>>>(NROWS, N3H, NEP, p_dembb, NEP,
                                          p_wide, NEP, nullptr, p_gidec, N3H,
                                          nullptr, 0);
    }
    cudaEventRecord(ev_join, s2);

    // main stream: encoder-side prep
    f2bf<<<512, 256>>>(W_hh_e, p_whe, N3H * NH);
    f2bf_slice<<<256, 256>>>(W_ih_e, NE, 0, NE, p_wie, NEP, N3H);
    f2bf_slice<<<512, 256>>>(W_ih_d, NE + NH, NE, NH, p_widc, NH, N3H);
    build_perm<<<1, NB>>>(lengths, p_perm, p_cnt);
    permute_h0<<<BH / 256, 256>>>(h0_enc, p_perm, p_hf, p_hb0);
    gather_emb_enc_bf<<<512, 256>>>(inputs, E_enc, p_embb);

    // ---- encoder input-side gates ----
    {
        dim3 grid(N3H / 128, (NB * NS) / 128);   // 24 x 128
        hgemm128<0><<<grid, 256>>>(NB * NS, N3H, NEP, p_embb, NEP, p_wie, NEP,
                                   b_ih_e, p_gienc, N3H, nullptr, 0);
    }

    // ---- encoder recurrence (length-sorted) ----
    dim3 grid_rec(N3H / TBN, NB / TBM);          // 48 x 4
    for (int t = 0; t < NS; t++) {
        hgemm<<<grid_rec, 128>>>(NB, N3H, NH, p_hb0, NH, p_whe, NH,
                                 b_hh_e, p_gh, N3H, p_cnt, t);
        gru_cell_enc<<<BH / 256, 256>>>(p_gienc, t, p_gh, p_hf, p_hb0,
                                        p_perm, p_cnt, lengths, p_ctx, p_ctxb);
    }

    // ---- decoder prologue ----
    hgemm<<<grid_rec, 128>>>(NB, N3H, NH, p_ctxb, NH, p_widc, NH,
                             b_ih_d, p_ctxgi, N3H, nullptr, 0);

    cudaStreamWaitEvent(0, ev_join, 0);

    // ---- decoder recurrence with overlapped per-step logits chunks ----
    dim3 grid_log(NTILN, 2);                     // 250 x 2 (256 rows per step)
    for (int t = 0; t < TD; t++) {
        const float* hp = (t == 0) ? p_ctx : p_hd;
        const bf16* hpb = (t == 0) ? p_ctxb : (p_hall + (size_t)(t - 1) * BH);
        hgemm<<<grid_rec, 128>>>(NB, N3H, NH, hpb, NH, p_whd, NH,
                                 b_hh_d, p_gh, N3H, nullptr, 0);
        gru_cell_dec<<<BH / 256, 256>>>(p_gidec, p_ctxgi, t, p_gh, hp, p_hd,
                                        p_hall + (size_t)t * BH);
        // stream the logits+CE chunk for step t on s2
        cudaEventRecord(ev_step, 0);
        cudaStreamWaitEvent(s2, ev_step, 0);
        hgemm128<1><<<grid_log, 256, 0, s2>>>(NROWS, NV, NH, p_hall, NH,
                                              p_wfc, NH, b_fc, nullptr, 0,
                                              p_cepart, t * NB);
    }
    cudaEventRecord(ev_log, s2);
    cudaStreamWaitEvent(0, ev_log, 0);

    // ---- CE finish ----
    target_dot<<<(NROWS * 32 + 255) / 256, 256>>>(p_hall, p_wfc, b_fc, targets, p_tgt);
    ce_reduce<<<(NROWS + 255) / 256, 256>>>(p_cepart, p_tgt, targets, p_ce, p_mask);
    final_loss_kernel<<<1, 256>>>(p_ce, p_mask, out);
}